// round 1
// baseline (speedup 1.0000x reference)
#include <cuda_runtime.h>

// ---------------------------------------------------------------------------
// LinearAttentionToeplitz  — fp32 SIMT baseline
//   B=8, T=2048, E=512.  Chunked causal linear attention:
//     P_c = mask(Q_c K_c^T)  (precomputed, chunk-parallel)
//     out_c = (Q_c S_prev + P_c V_c) / d ,  d_t = max(q_t.z_prev + rowsum(P)_t, eps)
//     S += K_c^T V_c ,  z += colsum(K_c)
//   Scan parallelized over (batch, 32-wide V-column group) = 128 CTAs.
// ---------------------------------------------------------------------------

#define BB 8
#define TT 2048
#define EE 512
#define CC 128          // chunk length
#define NCH 16          // TT / CC
#define EV 32           // v-columns per scan CTA
#define NG 16           // EE / EV
#define EPS_D 1e-3f
#define QSCALE 0.044194173824159216f   // 512^-0.5

// scratch (module-load allocation; allowed)
__device__ float g_Q[BB * TT * EE];
__device__ float g_K[BB * TT * EE];
__device__ float g_V[BB * TT * EE];
__device__ float g_A[BB * TT * EE];          // attention output pre o-proj
__device__ float g_P[BB * NCH * CC * CC];    // masked Q K^T per chunk
__device__ float g_RS[BB * TT];              // row sums of masked P

// ---------------------------------------------------------------------------
// Projection GEMM:  out[b,t,o] = sum_e w[o,e] * x[b,e,t] + bias[o]
//   mode 0: Q (raw, softmax later)   mode 1: K (exp)   mode 2: V (* toep[t])
// Tile 128(t) x 128(o), BK=16, 256 threads, 8x8 micro-tile.
// ---------------------------------------------------------------------------
__global__ __launch_bounds__(256) void proj_gemm(
    const float* __restrict__ x, const float* __restrict__ w,
    const float* __restrict__ bias, const float* __restrict__ toep, int mode)
{
    float* out = (mode == 0) ? g_Q : (mode == 1) ? g_K : g_V;
    __shared__ float Ws[16][129];   // [e][o]
    __shared__ float Xs[16][129];   // [e][t]
    const int b  = blockIdx.z;
    const int t0 = blockIdx.x * 128, o0 = blockIdx.y * 128;
    const int tid = threadIdx.x;
    const int tx = tid & 15, ty = tid >> 4;
    const float* xb = x + (size_t)b * EE * TT;

    float acc[8][8];
#pragma unroll
    for (int i = 0; i < 8; i++)
#pragma unroll
        for (int j = 0; j < 8; j++) acc[i][j] = 0.f;

    for (int k0 = 0; k0 < EE; k0 += 16) {
#pragma unroll
        for (int i = 0; i < 8; i++) {
            int li = tid + i * 256;
            int e = li & 15, o = li >> 4;
            Ws[e][o] = w[(size_t)(o0 + o) * EE + k0 + e];
        }
#pragma unroll
        for (int i = 0; i < 8; i++) {
            int li = tid + i * 256;
            int t = li & 127, e = li >> 7;
            Xs[e][t] = xb[(size_t)(k0 + e) * TT + t0 + t];
        }
        __syncthreads();
#pragma unroll
        for (int kk = 0; kk < 16; kk++) {
            float a[8], bv[8];
#pragma unroll
            for (int j = 0; j < 8; j++) a[j] = Ws[kk][ty * 8 + j];
#pragma unroll
            for (int i = 0; i < 8; i++) bv[i] = Xs[kk][tx + 16 * i];
#pragma unroll
            for (int i = 0; i < 8; i++)
#pragma unroll
                for (int j = 0; j < 8; j++) acc[i][j] += bv[i] * a[j];
        }
        __syncthreads();
    }

#pragma unroll
    for (int i = 0; i < 8; i++) {
        int t = t0 + tx + 16 * i;
        float tw = (mode == 2) ? toep[t] : 1.f;
        float* orow = out + ((size_t)b * TT + t) * EE + o0 + ty * 8;
        float v[8];
#pragma unroll
        for (int j = 0; j < 8; j++) {
            float vv = acc[i][j] + bias[o0 + ty * 8 + j];
            if (mode == 1) vv = expf(vv);
            else if (mode == 2) vv *= tw;
            v[j] = vv;
        }
        float4 p0 = make_float4(v[0], v[1], v[2], v[3]);
        float4 p1 = make_float4(v[4], v[5], v[6], v[7]);
        *(float4*)&orow[0] = p0;
        *(float4*)&orow[4] = p1;
    }
}

// ---------------------------------------------------------------------------
// Row softmax over E for Q, times E^-0.5.  One block per (b,t) row.
// ---------------------------------------------------------------------------
__global__ __launch_bounds__(256) void softmax_q()
{
    size_t row = blockIdx.x;
    float* r = g_Q + row * EE;
    int tid = threadIdx.x;
    float v0 = r[tid], v1 = r[tid + 256];
    __shared__ float red[256];
    red[tid] = fmaxf(v0, v1);
    __syncthreads();
    for (int s = 128; s > 0; s >>= 1) {
        if (tid < s) red[tid] = fmaxf(red[tid], red[tid + s]);
        __syncthreads();
    }
    float m = red[0];
    __syncthreads();
    float e0 = expf(v0 - m), e1 = expf(v1 - m);
    red[tid] = e0 + e1;
    __syncthreads();
    for (int s = 128; s > 0; s >>= 1) {
        if (tid < s) red[tid] += red[tid + s];
        __syncthreads();
    }
    float scale = QSCALE / red[0];
    r[tid] = e0 * scale;
    r[tid + 256] = e1 * scale;
}

// ---------------------------------------------------------------------------
// P = mask(Q_c K_c^T) per (b, chunk), plus row sums.  128x128x512 GEMM / CTA.
// ---------------------------------------------------------------------------
__global__ __launch_bounds__(256) void compute_P()
{
    const int c = blockIdx.x, b = blockIdx.y;
    const float* Qc = g_Q + ((size_t)b * TT + (size_t)c * CC) * EE;
    const float* Kc = g_K + ((size_t)b * TT + (size_t)c * CC) * EE;
    __shared__ float Qs[16][129];   // [e][t]
    __shared__ float Ks[16][129];   // [e][s]
    __shared__ float rs[CC];
    const int tid = threadIdx.x;
    const int tx = tid & 15, ty = tid >> 4;
    if (tid < CC) rs[tid] = 0.f;

    float acc[8][8];
#pragma unroll
    for (int i = 0; i < 8; i++)
#pragma unroll
        for (int j = 0; j < 8; j++) acc[i][j] = 0.f;

    for (int k0 = 0; k0 < EE; k0 += 16) {
#pragma unroll
        for (int i = 0; i < 8; i++) {
            int li = tid + i * 256;
            int e = li & 15, t = li >> 4;
            Qs[e][t] = Qc[(size_t)t * EE + k0 + e];
            Ks[e][t] = Kc[(size_t)t * EE + k0 + e];
        }
        __syncthreads();
#pragma unroll
        for (int kk = 0; kk < 16; kk++) {
            float a[8], bv[8];
#pragma unroll
            for (int i = 0; i < 8; i++) a[i] = Qs[kk][ty + 16 * i];
#pragma unroll
            for (int j = 0; j < 8; j++) bv[j] = Ks[kk][tx + 16 * j];
#pragma unroll
            for (int i = 0; i < 8; i++)
#pragma unroll
                for (int j = 0; j < 8; j++) acc[i][j] += a[i] * bv[j];
        }
        __syncthreads();
    }

    float* Pc = g_P + (size_t)(b * NCH + c) * CC * CC;
#pragma unroll
    for (int i = 0; i < 8; i++) {
        int t = ty + 16 * i;
        float rsum = 0.f;
#pragma unroll
        for (int j = 0; j < 8; j++) {
            int s = tx + 16 * j;
            float v = (s <= t) ? acc[i][j] : 0.f;
            Pc[(size_t)t * CC + s] = v;
            rsum += v;
        }
        atomicAdd(&rs[t], rsum);
    }
    __syncthreads();
    if (tid < CC) g_RS[(size_t)b * TT + (size_t)c * CC + tid] = rs[tid];
}

// ---------------------------------------------------------------------------
// Chunked scan.  Grid (NG, BB) = 128 CTAs, 256 threads.
// Shared: S[512][32] state slice, Vs[128][32], z[512], qz[128],
//         buf[128][129] (staging for Q-tiles / P^T / K-tiles).
// ---------------------------------------------------------------------------
#define SCAN_SMEM ((EE*EV + CC*EV + EE + CC + CC*129) * 4)

__global__ __launch_bounds__(256) void scan_kernel()
{
    const int g = blockIdx.x, b = blockIdx.y;
    extern __shared__ float sm[];
    float* S   = sm;                  // 512*32
    float* Vs  = S  + EE * EV;        // 128*32
    float* zs  = Vs + CC * EV;        // 512
    float* qz  = zs + EE;             // 128
    float* buf = qz + CC;             // 128*129

    const int tid = threadIdx.x;
    const int tx2 = tid & 31, ty2 = tid >> 5;    // t-lane, j-group (of 4)
    const int ex  = tid & 63, jy  = tid >> 6;    // e-lane, j-group (of 8)

    for (int i = tid; i < EE * EV; i += 256) S[i] = 0.f;
    for (int i = tid; i < EE; i += 256) zs[i] = 0.f;
    __syncthreads();

    const size_t bofs = (size_t)b * TT * EE;

    for (int c = 0; c < NCH; c++) {
        const float* Qc = g_Q + bofs + (size_t)c * CC * EE;
        const float* Kc = g_K + bofs + (size_t)c * CC * EE;
        const float* Vc = g_V + bofs + (size_t)c * CC * EE + g * EV;

        // load V chunk slice
#pragma unroll
        for (int i = 0; i < 16; i++) {
            int li = tid + i * 256;
            int j = li & 31, s = li >> 5;
            Vs[s * EV + j] = Vc[(size_t)s * EE + j];
        }

        float acc[4][4];
#pragma unroll
        for (int i = 0; i < 4; i++)
#pragma unroll
            for (int j = 0; j < 4; j++) acc[i][j] = 0.f;
        float qza[4] = {0.f, 0.f, 0.f, 0.f};

        // ---- Phase A: O += Q_c @ S_prev ; qz = Q_c . z_prev ----
        if (c > 0) {
            for (int eb = 0; eb < EE; eb += 32) {
                __syncthreads();   // buf reusable
#pragma unroll
                for (int i = 0; i < 16; i++) {
                    int li = tid + i * 256;
                    int e = li & 31, t = li >> 5;
                    buf[e * 129 + t] = Qc[(size_t)t * EE + eb + e];
                }
                __syncthreads();
#pragma unroll 4
                for (int e = 0; e < 32; e++) {
                    const float4 sv = *(const float4*)&S[(eb + e) * EV + ty2 * 4];
                    const float zv = zs[eb + e];
#pragma unroll
                    for (int i = 0; i < 4; i++) {
                        float qv = buf[e * 129 + tx2 + 32 * i];
                        acc[i][0] += qv * sv.x;
                        acc[i][1] += qv * sv.y;
                        acc[i][2] += qv * sv.z;
                        acc[i][3] += qv * sv.w;
                        qza[i]    += qv * zv;
                    }
                }
            }
        }
        __syncthreads();
        if (ty2 == 0) {
#pragma unroll
            for (int i = 0; i < 4; i++) qz[tx2 + 32 * i] = qza[i];
        }

        // ---- Phase B: O += P_c @ V_c  (stage P transposed) ----
        const float* Pc = g_P + (size_t)(b * NCH + c) * CC * CC;
#pragma unroll
        for (int i = 0; i < 64; i++) {
            int li = tid + i * 256;
            int s = li & 127, t = li >> 7;
            buf[s * 129 + t] = Pc[(size_t)t * CC + s];
        }
        __syncthreads();
#pragma unroll 2
        for (int s = 0; s < CC; s++) {
            const float4 vv = *(const float4*)&Vs[s * EV + ty2 * 4];
#pragma unroll
            for (int i = 0; i < 4; i++) {
                float pv = buf[s * 129 + tx2 + 32 * i];
                acc[i][0] += pv * vv.x;
                acc[i][1] += pv * vv.y;
                acc[i][2] += pv * vv.z;
                acc[i][3] += pv * vv.w;
            }
        }

        // ---- Phase C: divide by d, write out ----
        {
            const float* RSc = g_RS + (size_t)b * TT + (size_t)c * CC;
            float* Ac = g_A + bofs + (size_t)c * CC * EE + g * EV;
#pragma unroll
            for (int i = 0; i < 4; i++) {
                int t = tx2 + 32 * i;
                float d = fmaxf(qz[t] + RSc[t], EPS_D);
                float inv = 1.f / d;
                float4 o4 = make_float4(acc[i][0] * inv, acc[i][1] * inv,
                                        acc[i][2] * inv, acc[i][3] * inv);
                *(float4*)&Ac[(size_t)t * EE + ty2 * 4] = o4;
            }
        }

        // ---- Phase D: S += K_c^T V_c ; z += colsum(K_c) ----
        for (int eb = 0; eb < EE; eb += 128) {
            __syncthreads();   // previous buf readers done
#pragma unroll
            for (int i = 0; i < 64; i++) {
                int li = tid + i * 256;
                int e = li & 127, s = li >> 7;
                buf[s * 129 + e] = Kc[(size_t)s * EE + eb + e];
            }
            __syncthreads();
            float a0[8], a1[8];
#pragma unroll
            for (int j = 0; j < 8; j++) { a0[j] = 0.f; a1[j] = 0.f; }
            float z0 = 0.f, z1 = 0.f;
#pragma unroll 2
            for (int s = 0; s < CC; s++) {
                float k0 = buf[s * 129 + ex];
                float k1 = buf[s * 129 + ex + 64];
                const float4 v0 = *(const float4*)&Vs[s * EV + jy * 8];
                const float4 v1 = *(const float4*)&Vs[s * EV + jy * 8 + 4];
                a0[0] += k0 * v0.x; a0[1] += k0 * v0.y;
                a0[2] += k0 * v0.z; a0[3] += k0 * v0.w;
                a0[4] += k0 * v1.x; a0[5] += k0 * v1.y;
                a0[6] += k0 * v1.z; a0[7] += k0 * v1.w;
                a1[0] += k1 * v0.x; a1[1] += k1 * v0.y;
                a1[2] += k1 * v0.z; a1[3] += k1 * v0.w;
                a1[4] += k1 * v1.x; a1[5] += k1 * v1.y;
                a1[6] += k1 * v1.z; a1[7] += k1 * v1.w;
                z0 += k0; z1 += k1;
            }
            float* Sr0 = &S[(size_t)(eb + ex) * EV + jy * 8];
            float* Sr1 = &S[(size_t)(eb + ex + 64) * EV + jy * 8];
#pragma unroll
            for (int j = 0; j < 8; j++) { Sr0[j] += a0[j]; Sr1[j] += a1[j]; }
            if (jy == 0) { zs[eb + ex] += z0; zs[eb + ex + 64] += z1; }
        }
        __syncthreads();   // S/zs/Vs stable before next chunk
    }
}

// ---------------------------------------------------------------------------
// Output projection:  out[b,t,o] = sum_e A[b,t,e] * ow[o,e] + ob[o]
// ---------------------------------------------------------------------------
__global__ __launch_bounds__(256) void out_gemm(const float* __restrict__ ow,
                                                const float* __restrict__ ob,
                                                float* __restrict__ out)
{
    __shared__ float As[16][129];   // [e][t]
    __shared__ float Ws[16][129];   // [e][o]
    const int b  = blockIdx.z;
    const int t0 = blockIdx.x * 128, o0 = blockIdx.y * 128;
    const int tid = threadIdx.x;
    const int tx = tid & 15, ty = tid >> 4;
    const float* Ab = g_A + (size_t)b * TT * EE;

    float acc[8][8];
#pragma unroll
    for (int i = 0; i < 8; i++)
#pragma unroll
        for (int j = 0; j < 8; j++) acc[i][j] = 0.f;

    for (int k0 = 0; k0 < EE; k0 += 16) {
#pragma unroll
        for (int i = 0; i < 8; i++) {
            int li = tid + i * 256;
            int e = li & 15, t = li >> 4;
            As[e][t] = Ab[(size_t)(t0 + t) * EE + k0 + e];
        }
#pragma unroll
        for (int i = 0; i < 8; i++) {
            int li = tid + i * 256;
            int e = li & 15, o = li >> 4;
            Ws[e][o] = ow[(size_t)(o0 + o) * EE + k0 + e];
        }
        __syncthreads();
#pragma unroll
        for (int kk = 0; kk < 16; kk++) {
            float a[8], bv[8];
#pragma unroll
            for (int j = 0; j < 8; j++) a[j] = Ws[kk][ty * 8 + j];
#pragma unroll
            for (int i = 0; i < 8; i++) bv[i] = As[kk][tx + 16 * i];
#pragma unroll
            for (int i = 0; i < 8; i++)
#pragma unroll
                for (int j = 0; j < 8; j++) acc[i][j] += bv[i] * a[j];
        }
        __syncthreads();
    }

#pragma unroll
    for (int i = 0; i < 8; i++) {
        int t = t0 + tx + 16 * i;
        float* orow = out + ((size_t)b * TT + t) * EE + o0 + ty * 8;
        float v[8];
#pragma unroll
        for (int j = 0; j < 8; j++) v[j] = acc[i][j] + ob[o0 + ty * 8 + j];
        *(float4*)&orow[0] = make_float4(v[0], v[1], v[2], v[3]);
        *(float4*)&orow[4] = make_float4(v[4], v[5], v[6], v[7]);
    }
}

// ---------------------------------------------------------------------------
extern "C" void kernel_launch(void* const* d_in, const int* in_sizes, int n_in,
                              void* d_out, int out_size)
{
    (void)in_sizes; (void)n_in; (void)out_size;
    const float* x    = (const float*)d_in[0];
    const float* toep = (const float*)d_in[1];
    const float* q_w  = (const float*)d_in[2];
    const float* q_b  = (const float*)d_in[3];
    const float* k_w  = (const float*)d_in[4];
    const float* k_b  = (const float*)d_in[5];
    const float* v_w  = (const float*)d_in[6];
    const float* v_b  = (const float*)d_in[7];
    const float* o_w  = (const float*)d_in[8];
    const float* o_b  = (const float*)d_in[9];
    float* out = (float*)d_out;

    cudaFuncSetAttribute(scan_kernel,
                         cudaFuncAttributeMaxDynamicSharedMemorySize, SCAN_SMEM);

    dim3 gProj(TT / 128, EE / 128, BB);          // (16, 4, 8)
    proj_gemm<<<gProj, 256>>>(x, q_w, q_b, toep, 0);
    proj_gemm<<<gProj, 256>>>(x, k_w, k_b, toep, 1);
    proj_gemm<<<gProj, 256>>>(x, v_w, v_b, toep, 2);
    softmax_q<<<BB * TT, 256>>>();
    compute_P<<<dim3(NCH, BB), 256>>>();
    scan_kernel<<<dim3(NG, BB), 256, SCAN_SMEM>>>();
    out_gemm<<<gProj, 256>>>(o_w, o_b, out);
}

// round 2
// speedup vs baseline: 1.7719x; 1.7719x over previous
#include <cuda_runtime.h>
#include <cstdint>
#include <math.h>

#define BB 8
#define TT 2048
#define EE 512
#define CC 128
#define NCH 16
#define EPS_D 1e-3f
#define QSCALE 0.044194173824159216f   // 512^-0.5

// ---------------- device scratch ----------------
__device__ float g_Q[BB * TT * EE];
__device__ float g_K[BB * TT * EE];
__device__ float g_V[BB * TT * EE];
__device__ float g_A[BB * TT * EE];
__device__ float g_P[BB * NCH * CC * CC];
__device__ float g_RS[BB * TT];
__device__ float g_DI[BB * TT];
__device__ float g_ZC[BB * NCH * EE];
__device__ float g_SP[(size_t)BB * NCH * EE * EE];  // per-chunk K^T V partials
__device__ float g_SC[(size_t)BB * NCH * EE * EE];  // exclusive prefix of g_SP

// ---------------- tf32 helpers ----------------
__device__ __forceinline__ float tf32r(float v) {
    uint32_t u;
    asm("cvt.rna.tf32.f32 %0, %1;" : "=r"(u) : "f"(v));
    return __uint_as_float(u);
}

__device__ __forceinline__ void mma8(float* c, const uint32_t* a, const uint32_t* b) {
    asm("mma.sync.aligned.m16n8k8.row.col.f32.tf32.tf32.f32 "
        "{%0,%1,%2,%3}, {%4,%5,%6,%7}, {%8,%9}, {%0,%1,%2,%3};"
        : "+f"(c[0]), "+f"(c[1]), "+f"(c[2]), "+f"(c[3])
        : "r"(a[0]), "r"(a[1]), "r"(a[2]), "r"(a[3]), "r"(b[0]), "r"(b[1]));
}

// swizzled smem word address for tile [k(16)][t(128)]
__device__ __forceinline__ int swz(int k, int t) {
    return (k << 7) + (t ^ ((((k & 3) ^ ((k >> 2) & 3))) << 3));
}

// ---- staging: element (t, k) = g[k*ld + t]  (lanes along t -> coalesced) ----
__device__ __forceinline__ void stage_T(const float* __restrict__ g, int ld,
                                        float* __restrict__ hi, float* __restrict__ lo,
                                        int tid) {
#pragma unroll
    for (int i = 0; i < 8; i++) {
        int li = tid + i * 256;
        int t = li & 127, k = li >> 7;
        float v = g[(size_t)k * ld + t];
        float h = tf32r(v);
        int a = swz(k, t);
        hi[a] = h;
        lo[a] = v - h;
    }
}

// ---- staging: element (n, k) = g[n*ld + k]  (float4 along k) ----
__device__ __forceinline__ void stage_N(const float* __restrict__ g, int ld,
                                        float* __restrict__ hi, float* __restrict__ lo,
                                        int tid) {
    int q = tid & 3, n = tid >> 2;
#pragma unroll
    for (int i = 0; i < 2; i++) {
        int nn = n + i * 64;
        const float4 v4 = *(const float4*)(g + (size_t)nn * ld + q * 4);
        float vv[4] = {v4.x, v4.y, v4.z, v4.w};
#pragma unroll
        for (int j = 0; j < 4; j++) {
            int k = q * 4 + j;
            float v = vv[j];
            float h = tf32r(v);
            int a = swz(k, nn);
            hi[a] = h;
            lo[a] = v - h;
        }
    }
}

// ---- per-ktile compute: 3xTF32 (hh + hl + lh) ----
__device__ __forceinline__ void compute_ktile(
    float (&acc)[4][4][4],
    const float* __restrict__ Ah, const float* __restrict__ Al,
    const float* __restrict__ Bh, const float* __restrict__ Bl,
    const int* rm, const int* rb, const int (&off)[2][2], const int (&xr)[2][2])
{
#pragma unroll
    for (int ks = 0; ks < 2; ks++) {
        uint32_t bh[4][2], bl[4][2];
#pragma unroll
        for (int in = 0; in < 4; in++) {
            int a0 = off[ks][0] + (rb[in] ^ xr[ks][0]);
            int a1 = off[ks][1] + (rb[in] ^ xr[ks][1]);
            bh[in][0] = __float_as_uint(Bh[a0]);
            bh[in][1] = __float_as_uint(Bh[a1]);
            bl[in][0] = __float_as_uint(Bl[a0]);
            bl[in][1] = __float_as_uint(Bl[a1]);
        }
        uint32_t af[4][4];
#pragma unroll
        for (int im = 0; im < 4; im++)
#pragma unroll
            for (int r = 0; r < 4; r++) {
                int d = r & 1, gg = r >> 1;
                af[im][r] = __float_as_uint(Ah[off[ks][gg] + (rm[im * 2 + d] ^ xr[ks][gg])]);
            }
#pragma unroll
        for (int im = 0; im < 4; im++)
#pragma unroll
            for (int in = 0; in < 4; in++) mma8(acc[im][in], af[im], bh[in]);
#pragma unroll
        for (int im = 0; im < 4; im++)
#pragma unroll
            for (int in = 0; in < 4; in++) mma8(acc[im][in], af[im], bl[in]);
#pragma unroll
        for (int im = 0; im < 4; im++)
#pragma unroll
            for (int r = 0; r < 4; r++) {
                int d = r & 1, gg = r >> 1;
                af[im][r] = __float_as_uint(Al[off[ks][gg] + (rm[im * 2 + d] ^ xr[ks][gg])]);
            }
#pragma unroll
        for (int im = 0; im < 4; im++)
#pragma unroll
            for (int in = 0; in < 4; in++) mma8(acc[im][in], af[im], bh[in]);
    }
}

#define GEMM_PRE()                                                        \
    const int tid = threadIdx.x;                                          \
    const int lane = tid & 31, wid = tid >> 5;                            \
    const int warpM = (wid & 1) * 64, warpN = (wid >> 1) * 32;            \
    const int lq = lane & 3, lr = lane >> 2;                              \
    int rm[8], rb[4], off[2][2], xr[2][2];                                \
    _Pragma("unroll") for (int im = 0; im < 4; im++)                      \
        _Pragma("unroll") for (int d = 0; d < 2; d++)                     \
            rm[im * 2 + d] = warpM + im * 16 + d * 8 + lr;                \
    _Pragma("unroll") for (int in = 0; in < 4; in++)                      \
        rb[in] = warpN + in * 8 + lr;                                     \
    _Pragma("unroll") for (int ks = 0; ks < 2; ks++)                      \
        _Pragma("unroll") for (int gg = 0; gg < 2; gg++) {                \
            off[ks][gg] = (ks * 8 + gg * 4 + lq) << 7;                    \
            xr[ks][gg] = ((lq ^ (ks * 2 + gg)) & 3) << 3;                 \
        }                                                                 \
    float acc[4][4][4];                                                   \
    _Pragma("unroll") for (int im = 0; im < 4; im++)                      \
        _Pragma("unroll") for (int in = 0; in < 4; in++)                  \
            _Pragma("unroll") for (int r = 0; r < 4; r++)                 \
                acc[im][in][r] = 0.f;                                     \
    __shared__ float sAh[2048], sAl[2048], sBh[2048], sBl[2048];

// ---------------------------------------------------------------------------
// Projections: out[b,t,o] = xt @ w^T + b;  mode 0:Q raw  1:K exp  2:V*toep
// ---------------------------------------------------------------------------
__global__ __launch_bounds__(256, 2) void proj_mma(
    const float* __restrict__ x, const float* __restrict__ w,
    const float* __restrict__ bias, const float* __restrict__ toep, int mode)
{
    float* out = (mode == 0) ? g_Q : (mode == 1) ? g_K : g_V;
    const int b = blockIdx.z, t0 = blockIdx.x * 128, o0 = blockIdx.y * 128;
    GEMM_PRE();
    const float* xb = x + (size_t)b * EE * TT + t0;
    const float* wb = w + (size_t)o0 * EE;
    for (int k0 = 0; k0 < EE; k0 += 16) {
        stage_T(xb + (size_t)k0 * TT, TT, sAh, sAl, tid);
        stage_N(wb + k0, EE, sBh, sBl, tid);
        __syncthreads();
        compute_ktile(acc, sAh, sAl, sBh, sBl, rm, rb, off, xr);
        __syncthreads();
    }
#pragma unroll
    for (int im = 0; im < 4; im++)
#pragma unroll
        for (int d = 0; d < 2; d++) {
            int r = rm[im * 2 + d];
            int t = t0 + r;
            float tw = (mode == 2) ? toep[t] : 1.f;
            float* orow = out + ((size_t)b * TT + t) * EE + o0;
#pragma unroll
            for (int in = 0; in < 4; in++) {
                int cc = warpN + in * 8 + lq * 2;
                float v0 = acc[im][in][d * 2 + 0] + bias[o0 + cc];
                float v1 = acc[im][in][d * 2 + 1] + bias[o0 + cc + 1];
                if (mode == 1) { v0 = expf(v0); v1 = expf(v1); }
                else if (mode == 2) { v0 *= tw; v1 *= tw; }
                *(float2*)&orow[cc] = make_float2(v0, v1);
            }
        }
}

// ---------------------------------------------------------------------------
// Row softmax over E for Q (* E^-0.5)
// ---------------------------------------------------------------------------
__global__ __launch_bounds__(256) void softmax_q()
{
    size_t row = blockIdx.x;
    float* r = g_Q + row * EE;
    int tid = threadIdx.x;
    float v0 = r[tid], v1 = r[tid + 256];
    __shared__ float red[256];
    red[tid] = fmaxf(v0, v1);
    __syncthreads();
    for (int s = 128; s > 0; s >>= 1) {
        if (tid < s) red[tid] = fmaxf(red[tid], red[tid + s]);
        __syncthreads();
    }
    float m = red[0];
    __syncthreads();
    float e0 = expf(v0 - m), e1 = expf(v1 - m);
    red[tid] = e0 + e1;
    __syncthreads();
    for (int s = 128; s > 0; s >>= 1) {
        if (tid < s) red[tid] += red[tid + s];
        __syncthreads();
    }
    float scale = QSCALE / red[0];
    r[tid] = e0 * scale;
    r[tid + 256] = e1 * scale;
}

// ---------------------------------------------------------------------------
// P = mask(Q_c K_c^T) + row sums.  one CTA per (chunk, batch)
// ---------------------------------------------------------------------------
__global__ __launch_bounds__(256, 2) void p_mma()
{
    const int cI = blockIdx.x, b = blockIdx.y;
    GEMM_PRE();
    __shared__ float srs[CC];
    if (tid < CC) srs[tid] = 0.f;
    const float* Qc = g_Q + ((size_t)b * TT + (size_t)cI * CC) * EE;
    const float* Kc = g_K + ((size_t)b * TT + (size_t)cI * CC) * EE;
    for (int k0 = 0; k0 < EE; k0 += 16) {
        stage_N(Qc + k0, EE, sAh, sAl, tid);
        stage_N(Kc + k0, EE, sBh, sBl, tid);
        __syncthreads();
        compute_ktile(acc, sAh, sAl, sBh, sBl, rm, rb, off, xr);
        __syncthreads();
    }
    float* Pc = g_P + (size_t)(b * NCH + cI) * CC * CC;
#pragma unroll
    for (int im = 0; im < 4; im++)
#pragma unroll
        for (int d = 0; d < 2; d++) {
            int r = rm[im * 2 + d];
            float rsum = 0.f;
#pragma unroll
            for (int in = 0; in < 4; in++) {
                int cc = warpN + in * 8 + lq * 2;
                float v0 = (cc <= r)     ? acc[im][in][d * 2 + 0] : 0.f;
                float v1 = (cc + 1 <= r) ? acc[im][in][d * 2 + 1] : 0.f;
                rsum += v0 + v1;
                *(float2*)&Pc[(size_t)r * CC + cc] = make_float2(v0, v1);
            }
            atomicAdd(&srs[r], rsum);
        }
    __syncthreads();
    if (tid < CC) g_RS[(size_t)b * TT + (size_t)cI * CC + tid] = srs[tid];
}

// ---------------------------------------------------------------------------
// Per-chunk K^T V partials:  g_SP[b,c] = K_c^T V_c   (512x512, K=128)
// ---------------------------------------------------------------------------
__global__ __launch_bounds__(256, 2) void ktv_mma()
{
    const int tile = blockIdx.x, cI = blockIdx.y, b = blockIdx.z;
    const int tm = (tile & 3) * 128, tn = (tile >> 2) * 128;
    GEMM_PRE();
    const float* Kc = g_K + ((size_t)b * TT + (size_t)cI * CC) * EE + tm;
    const float* Vc = g_V + ((size_t)b * TT + (size_t)cI * CC) * EE + tn;
    for (int k0 = 0; k0 < CC; k0 += 16) {
        stage_T(Kc + (size_t)k0 * EE, EE, sAh, sAl, tid);
        stage_T(Vc + (size_t)k0 * EE, EE, sBh, sBl, tid);
        __syncthreads();
        compute_ktile(acc, sAh, sAl, sBh, sBl, rm, rb, off, xr);
        __syncthreads();
    }
    float* Sp = g_SP + ((size_t)(b * NCH + cI) * EE) * EE;
#pragma unroll
    for (int im = 0; im < 4; im++)
#pragma unroll
        for (int d = 0; d < 2; d++) {
            int r = tm + rm[im * 2 + d];
#pragma unroll
            for (int in = 0; in < 4; in++) {
                int cc = tn + warpN + in * 8 + lq * 2;
                *(float2*)&Sp[(size_t)r * EE + cc] =
                    make_float2(acc[im][in][d * 2 + 0], acc[im][in][d * 2 + 1]);
            }
        }
}

// ---------------------------------------------------------------------------
// Exclusive prefix over chunks:  g_SC[b,c] = sum_{c'<c} g_SP[b,c']
// ---------------------------------------------------------------------------
__global__ __launch_bounds__(256) void prefix_S()
{
    int gid = blockIdx.x * 256 + threadIdx.x;     // 524288 threads
    int b = gid >> 16;
    int p4 = gid & 65535;
    size_t base = ((size_t)b * NCH) * EE * EE + (size_t)p4 * 4;
    float4 run = make_float4(0.f, 0.f, 0.f, 0.f);
    for (int c = 0; c < NCH; c++) {
        size_t o = base + (size_t)c * EE * EE;
        *(float4*)(g_SC + o) = run;
        float4 s = *(const float4*)(g_SP + o);
        run.x += s.x; run.y += s.y; run.z += s.z; run.w += s.w;
    }
}

// ---------------------------------------------------------------------------
// z exclusive prefix:  g_ZC[b,c,e] = sum_{c'<c} colsum(K_{c'})[e]
// ---------------------------------------------------------------------------
__global__ __launch_bounds__(512) void z_prefix()
{
    int b = blockIdx.x, e = threadIdx.x;
    float run = 0.f;
    for (int c = 0; c < NCH; c++) {
        g_ZC[((size_t)b * NCH + c) * EE + e] = run;
        const float* kb = g_K + ((size_t)b * TT + (size_t)c * CC) * EE + e;
#pragma unroll 8
        for (int s = 0; s < CC; s++) run += kb[(size_t)s * EE];
    }
}

// ---------------------------------------------------------------------------
// Denominator:  g_DI[row] = 1 / max(q . z_prev + rowsum(P), eps)
// ---------------------------------------------------------------------------
__global__ __launch_bounds__(256) void dinv_kernel()
{
    int w = blockIdx.x * 8 + (threadIdx.x >> 5);   // global row
    int lane = threadIdx.x & 31;
    int b = w >> 11, t = w & 2047, c = t >> 7;
    const float* q = g_Q + (size_t)w * EE;
    const float* z = g_ZC + ((size_t)b * NCH + c) * EE;
    float s = 0.f;
#pragma unroll
    for (int i = 0; i < 16; i++) s += q[lane + 32 * i] * z[lane + 32 * i];
#pragma unroll
    for (int o = 16; o > 0; o >>= 1) s += __shfl_xor_sync(0xffffffffu, s, o);
    if (lane == 0) {
        float d = fmaxf(s + g_RS[w], EPS_D);
        g_DI[w] = 1.f / d;
    }
}

// ---------------------------------------------------------------------------
// O = (Q_c @ S_cum + P_c @ V_c) * dinv    one CTA per (ntile, chunk, batch)
// ---------------------------------------------------------------------------
__global__ __launch_bounds__(256, 2) void qspv_mma()
{
    const int n0 = blockIdx.x * 128, cI = blockIdx.y, b = blockIdx.z;
    GEMM_PRE();
    if (cI > 0) {
        const float* Qc = g_Q + ((size_t)b * TT + (size_t)cI * CC) * EE;
        const float* Sc = g_SC + ((size_t)(b * NCH + cI) * EE) * EE + n0;
        for (int k0 = 0; k0 < EE; k0 += 16) {
            stage_N(Qc + k0, EE, sAh, sAl, tid);
            stage_T(Sc + (size_t)k0 * EE, EE, sBh, sBl, tid);
            __syncthreads();
            compute_ktile(acc, sAh, sAl, sBh, sBl, rm, rb, off, xr);
            __syncthreads();
        }
    }
    const float* Pc = g_P + (size_t)(b * NCH + cI) * CC * CC;
    const float* Vc = g_V + ((size_t)b * TT + (size_t)cI * CC) * EE + n0;
    for (int k0 = 0; k0 < CC; k0 += 16) {
        stage_N(Pc + k0, CC, sAh, sAl, tid);
        stage_T(Vc + (size_t)k0 * EE, EE, sBh, sBl, tid);
        __syncthreads();
        compute_ktile(acc, sAh, sAl, sBh, sBl, rm, rb, off, xr);
        __syncthreads();
    }
#pragma unroll
    for (int im = 0; im < 4; im++)
#pragma unroll
        for (int d = 0; d < 2; d++) {
            int r = rm[im * 2 + d];
            size_t row = (size_t)b * TT + (size_t)cI * CC + r;
            float di = g_DI[row];
            float* arow = g_A + row * EE + n0;
#pragma unroll
            for (int in = 0; in < 4; in++) {
                int cc = warpN + in * 8 + lq * 2;
                *(float2*)&arow[cc] = make_float2(acc[im][in][d * 2 + 0] * di,
                                                  acc[im][in][d * 2 + 1] * di);
            }
        }
}

// ---------------------------------------------------------------------------
// Output projection:  out = A @ o_w^T + o_b
// ---------------------------------------------------------------------------
__global__ __launch_bounds__(256, 2) void out_mma(
    const float* __restrict__ ow, const float* __restrict__ ob,
    float* __restrict__ out)
{
    const int b = blockIdx.z, t0 = blockIdx.x * 128, o0 = blockIdx.y * 128;
    GEMM_PRE();
    const float* Ab = g_A + ((size_t)b * TT + t0) * EE;
    const float* wb = ow + (size_t)o0 * EE;
    for (int k0 = 0; k0 < EE; k0 += 16) {
        stage_N(Ab + k0, EE, sAh, sAl, tid);
        stage_N(wb + k0, EE, sBh, sBl, tid);
        __syncthreads();
        compute_ktile(acc, sAh, sAl, sBh, sBl, rm, rb, off, xr);
        __syncthreads();
    }
#pragma unroll
    for (int im = 0; im < 4; im++)
#pragma unroll
        for (int d = 0; d < 2; d++) {
            int t = t0 + rm[im * 2 + d];
            float* orow = out + ((size_t)b * TT + t) * EE + o0;
#pragma unroll
            for (int in = 0; in < 4; in++) {
                int cc = warpN + in * 8 + lq * 2;
                *(float2*)&orow[cc] = make_float2(acc[im][in][d * 2 + 0] + ob[o0 + cc],
                                                  acc[im][in][d * 2 + 1] + ob[o0 + cc + 1]);
            }
        }
}

// ---------------------------------------------------------------------------
extern "C" void kernel_launch(void* const* d_in, const int* in_sizes, int n_in,
                              void* d_out, int out_size)
{
    (void)in_sizes; (void)n_in; (void)out_size;
    const float* x    = (const float*)d_in[0];
    const float* toep = (const float*)d_in[1];
    const float* q_w  = (const float*)d_in[2];
    const float* q_b  = (const float*)d_in[3];
    const float* k_w  = (const float*)d_in[4];
    const float* k_b  = (const float*)d_in[5];
    const float* v_w  = (const float*)d_in[6];
    const float* v_b  = (const float*)d_in[7];
    const float* o_w  = (const float*)d_in[8];
    const float* o_b  = (const float*)d_in[9];
    float* out = (float*)d_out;

    dim3 gProj(TT / 128, EE / 128, BB);            // (16,4,8)
    proj_mma<<<gProj, 256>>>(x, q_w, q_b, toep, 0);
    proj_mma<<<gProj, 256>>>(x, k_w, k_b, toep, 1);
    proj_mma<<<gProj, 256>>>(x, v_w, v_b, toep, 2);
    softmax_q<<<BB * TT, 256>>>();
    p_mma<<<dim3(NCH, BB), 256>>>();
    z_prefix<<<BB, 512>>>();
    ktv_mma<<<dim3(16, NCH, BB), 256>>>();
    prefix_S<<<2048, 256>>>();
    dinv_kernel<<<BB * TT / 8, 256>>>();
    qspv_mma<<<dim3(EE / 128, NCH, BB), 256>>>();
    out_mma<<<gProj, 256>>>(o_w, o_b, out);
}